// round 13
// baseline (speedup 1.0000x reference)
#include <cuda_runtime.h>
#include <math.h>

#define N_BATCH 8
#define T_SEQ   2048
#define DMODEL  512
#define NHEAD   8
#define HDIM    64
#define M_ROWS  (N_BATCH*T_SEQ)   // 16384
#define EQKV    (3*DMODEL)        // 1536

// Scratch (no cudaMalloc allowed)
__device__ float g_qkv[(size_t)M_ROWS*EQKV];    // [n*T+t][1536] : [q(512) | k(512) | v(512)], each h*64+d
__device__ float g_attn[(size_t)M_ROWS*DMODEL]; // [n*T+t][512]

// ---------------------------------------------------------------------------
// Vanilla NT SGEMM:  C[m][e] = sum_k A[m][k] * B[e][k]  (+ bias[e] if given)
// A: [M][K] row-major, B: [Nc][K] row-major, C: [M][Nc] row-major.
// 128x128 tile, BK=8, 256 threads, 8x8 microtile.
// ---------------------------------------------------------------------------
#define BM 128
#define BN 128
#define BK 8

__global__ void __launch_bounds__(256) sgemm_nt_kernel(
    const float* __restrict__ A, const float* __restrict__ B,
    float* __restrict__ C, int K, int Nc, const float* __restrict__ bias)
{
    __shared__ __align__(16) float As[BK][BM];
    __shared__ __align__(16) float Bs[BK][BN];

    const int tid = threadIdx.x;
    const int tx  = tid & 15;        // 0..15  -> 8 cols each
    const int ty  = tid >> 4;        // 0..15  -> 8 rows each
    const int lr  = tid >> 1;        // load row 0..127
    const int lc  = (tid & 1) * 4;   // load col 0 or 4

    const float* Ap = A + ((size_t)blockIdx.y*BM + lr)*K + lc;
    const float* Bp = B + ((size_t)blockIdx.x*BN + lr)*K + lc;

    float acc[8][8];
    #pragma unroll
    for (int i = 0; i < 8; i++)
        #pragma unroll
        for (int j = 0; j < 8; j++) acc[i][j] = 0.f;

    for (int k0 = 0; k0 < K; k0 += BK) {
        float4 a4 = *reinterpret_cast<const float4*>(Ap + k0);
        float4 b4 = *reinterpret_cast<const float4*>(Bp + k0);
        As[lc+0][lr] = a4.x; As[lc+1][lr] = a4.y; As[lc+2][lr] = a4.z; As[lc+3][lr] = a4.w;
        Bs[lc+0][lr] = b4.x; Bs[lc+1][lr] = b4.y; Bs[lc+2][lr] = b4.z; Bs[lc+3][lr] = b4.w;
        __syncthreads();
        #pragma unroll
        for (int kk = 0; kk < BK; kk++) {
            float4 a0 = *reinterpret_cast<const float4*>(&As[kk][ty*8]);
            float4 a1 = *reinterpret_cast<const float4*>(&As[kk][ty*8+4]);
            float4 b0 = *reinterpret_cast<const float4*>(&Bs[kk][tx*8]);
            float4 b1 = *reinterpret_cast<const float4*>(&Bs[kk][tx*8+4]);
            float ar[8] = {a0.x,a0.y,a0.z,a0.w,a1.x,a1.y,a1.z,a1.w};
            float br[8] = {b0.x,b0.y,b0.z,b0.w,b1.x,b1.y,b1.z,b1.w};
            #pragma unroll
            for (int i = 0; i < 8; i++)
                #pragma unroll
                for (int j = 0; j < 8; j++)
                    acc[i][j] += ar[i]*br[j];
        }
        __syncthreads();
    }

    const int mbase = blockIdx.y*BM + ty*8;
    const int ebase = blockIdx.x*BN + tx*8;
    #pragma unroll
    for (int i = 0; i < 8; i++) {
        const int m = mbase + i;
        #pragma unroll
        for (int j = 0; j < 8; j++) {
            const int e = ebase + j;
            float v = acc[i][j];
            if (bias) v += bias[e];
            C[(size_t)m*Nc + e] = v;
        }
    }
}

// ---------------------------------------------------------------------------
// RoPE in place on the q and k sections of g_qkv.
// One thread per (n, t, h, i):  linear id over 8*2048*8*32 = 4194304.
//   i  = id & 31          (freq / dim-pair index, 0..31)
//   h  = (id >> 5) & 7
//   t  = (id >> 8) & 2047
//   n  = id >> 19
// pair (d=i, d=i+32):  n1 = v1*cos - v2*sin ; n2 = v2*cos + v1*sin
// inv_freq[i] = 10000^(-i/32); trig fully in double to remove any
// fast-math/range-reduction variable.
// ---------------------------------------------------------------------------
__global__ void rope_inplace_kernel()
{
    const int id = blockIdx.x*blockDim.x + threadIdx.x;
    const int i  = id & 31;
    const int h  = (id >> 5) & 7;
    const int t  = (id >> 8) & (T_SEQ - 1);
    const int n  = id >> 19;

    const double inv = pow(10000.0, -(double)i / 32.0);
    const double ang = (double)t * inv;
    const float  c   = (float)cos(ang);
    const float  s   = (float)sin(ang);

    float* p = g_qkv + ((size_t)(n*T_SEQ + t))*EQKV + h*HDIM;

    // q section (offset 0)
    {
        float v1 = p[i], v2 = p[i + 32];
        p[i]      = v1*c - v2*s;
        p[i + 32] = v2*c + v1*s;
    }
    // k section (offset DMODEL)
    {
        float v1 = p[DMODEL + i], v2 = p[DMODEL + i + 32];
        p[DMODEL + i]      = v1*c - v2*s;
        p[DMODEL + i + 32] = v2*c + v1*s;
    }
}

// ---------------------------------------------------------------------------
// Naive banded attention, register-only, one WARP per query row (n, h, i).
// Window: j - i in [-127, 128]  ->  j in [i-127, i+128], 256 candidates.
// Lane l owns output dims (2l, 2l+1).
// For each candidate key j:
//   - every lane computes partial dot q[2l..]*k[2l..], warp bfly-reduce -> score
//   - score*0.125, online softmax update (m, den, acc float2) identically on all lanes
// Output: g_attn[(n*T+i)][h*64 + 2l .. +1] = acc / den
// Warps of one CTA = 8 consecutive i of the same (n,h) -> overlapping k/v
// windows stay hot in L1.
// ---------------------------------------------------------------------------
__global__ void __launch_bounds__(256) attn_naive_kernel()
{
    const int gwarp = (blockIdx.x * blockDim.x + threadIdx.x) >> 5;
    const int l     = threadIdx.x & 31;
    const int i     = gwarp & (T_SEQ - 1);     // query position
    const int nh    = gwarp >> 11;             // 0..63
    const int n     = nh >> 3;
    const int h     = nh & 7;

    const float* base = g_qkv + (size_t)n*T_SEQ*EQKV + h*HDIM;

    const float2 qv = *reinterpret_cast<const float2*>(base + (size_t)i*EQKV + 2*l);

    float  mx  = -1e30f;
    float  den = 0.f;
    float2 acc = make_float2(0.f, 0.f);

    #pragma unroll 4
    for (int jj = 0; jj < 256; jj++) {
        const int j = i - 127 + jj;
        if (j < 0 || j >= T_SEQ) continue;     // uniform across warp

        const float* krow = base + (size_t)j*EQKV + DMODEL;
        const float2 kv = *reinterpret_cast<const float2*>(krow + 2*l);
        float part = qv.x*kv.x + qv.y*kv.y;
        #pragma unroll
        for (int o = 16; o > 0; o >>= 1)
            part += __shfl_xor_sync(0xffffffffu, part, o);
        const float sc = part * 0.125f;        // full dot, known to all lanes

        const float2 vv = *reinterpret_cast<const float2*>(krow + DMODEL + 2*l);

        const float mnew  = fmaxf(mx, sc);
        const float scale = __expf(mx - mnew);
        const float p     = __expf(sc - mnew);
        den   = den*scale + p;
        acc.x = acc.x*scale + p*vv.x;
        acc.y = acc.y*scale + p*vv.y;
        mx    = mnew;
    }

    const float inv = 1.f / den;
    float* optr = g_attn + ((size_t)(n*T_SEQ + i))*DMODEL + h*HDIM + 2*l;
    optr[0] = acc.x * inv;
    optr[1] = acc.y * inv;
}

// ---------------------------------------------------------------------------
extern "C" void kernel_launch(void* const* d_in, const int* in_sizes, int n_in,
                              void* d_out, int out_size)
{
    // Bind inputs by element count (robust to ordering); positional fallback.
    // x: 8388608, Wqkv: 786432, Wout: 262144, bout: 512 (or 4x if bytes).
    const float *x = nullptr, *Wqkv = nullptr, *Wout = nullptr, *bout = nullptr;
    for (int i = 0; i < n_in; i++) {
        long long s = in_sizes[i];
        const float* p = (const float*)d_in[i];
        if      (s == 8388608LL || s == 33554432LL) x    = p;
        else if (s == 786432LL  || s == 3145728LL)  Wqkv = p;
        else if (s == 262144LL  || s == 1048576LL)  Wout = p;
        else if (s == 512LL     || s == 2048LL)     bout = p;
    }
    if (!x    && n_in > 0) x    = (const float*)d_in[0];
    if (!Wqkv && n_in > 1) Wqkv = (const float*)d_in[1];
    if (!Wout && n_in > 2) Wout = (const float*)d_in[2];
    if (!bout && n_in > 3) bout = (const float*)d_in[3];

    float* out = (float*)d_out;
    (void)out_size;

    float* qkv_ptr  = nullptr;
    float* attn_ptr = nullptr;
    cudaGetSymbolAddress((void**)&qkv_ptr,  g_qkv);
    cudaGetSymbolAddress((void**)&attn_ptr, g_attn);

    // 1. QKV projection: g_qkv[m][1536] = x[m][:] . Wqkv[e][:]
    {
        dim3 g(EQKV/BN, M_ROWS/BM);   // (12, 128)
        sgemm_nt_kernel<<<g, 256>>>(x, Wqkv, qkv_ptr, DMODEL, EQKV, nullptr);
    }

    // 2. RoPE in place on q,k sections of g_qkv
    {
        const int total = N_BATCH * T_SEQ * NHEAD * 32;  // 4194304
        rope_inplace_kernel<<<total/256, 256>>>();
    }

    // 3. Banded attention (warp per query row) -> g_attn
    {
        const int total_warps = N_BATCH * NHEAD * T_SEQ;   // 131072
        attn_naive_kernel<<<total_warps/8, 256>>>();
    }

    // 4. Output projection + bias
    {
        dim3 g(DMODEL/BN, M_ROWS/BM);  // (4, 128)
        sgemm_nt_kernel<<<g, 256>>>(attn_ptr, Wout, out, DMODEL, DMODEL, bout);
    }
}

// round 14
// speedup vs baseline: 1.3989x; 1.3989x over previous
#include <cuda_runtime.h>
#include <math.h>

#define N_BATCH 8
#define T_SEQ   2048
#define DMODEL  512
#define NHEAD   8
#define HDIM    64
#define M_ROWS  (N_BATCH*T_SEQ)   // 16384
#define EQKV    (3*DMODEL)        // 1536

// Scratch (no cudaMalloc allowed)
__device__ float g_qkv[(size_t)M_ROWS*EQKV];    // [n*T+t][1536] : [q(512) | k(512) | v(512)], each h*64+d
__device__ float g_attn[(size_t)M_ROWS*DMODEL]; // [n*T+t][512]

// ---------------------------------------------------------------------------
// Vanilla NT SGEMM:  C[m][e] = sum_k A[m][k] * B[e][k]  (+ bias[e] if given)
// A: [M][K] row-major, B: [Nc][K] row-major, C: [M][Nc] row-major.
// 128x128 tile, BK=8, 256 threads, 8x8 microtile.  (UNCHANGED from passing R13)
// ---------------------------------------------------------------------------
#define BM 128
#define BN 128
#define BK 8

__global__ void __launch_bounds__(256) sgemm_nt_kernel(
    const float* __restrict__ A, const float* __restrict__ B,
    float* __restrict__ C, int K, int Nc, const float* __restrict__ bias)
{
    __shared__ __align__(16) float As[BK][BM];
    __shared__ __align__(16) float Bs[BK][BN];

    const int tid = threadIdx.x;
    const int tx  = tid & 15;        // 0..15  -> 8 cols each
    const int ty  = tid >> 4;        // 0..15  -> 8 rows each
    const int lr  = tid >> 1;        // load row 0..127
    const int lc  = (tid & 1) * 4;   // load col 0 or 4

    const float* Ap = A + ((size_t)blockIdx.y*BM + lr)*K + lc;
    const float* Bp = B + ((size_t)blockIdx.x*BN + lr)*K + lc;

    float acc[8][8];
    #pragma unroll
    for (int i = 0; i < 8; i++)
        #pragma unroll
        for (int j = 0; j < 8; j++) acc[i][j] = 0.f;

    for (int k0 = 0; k0 < K; k0 += BK) {
        float4 a4 = *reinterpret_cast<const float4*>(Ap + k0);
        float4 b4 = *reinterpret_cast<const float4*>(Bp + k0);
        As[lc+0][lr] = a4.x; As[lc+1][lr] = a4.y; As[lc+2][lr] = a4.z; As[lc+3][lr] = a4.w;
        Bs[lc+0][lr] = b4.x; Bs[lc+1][lr] = b4.y; Bs[lc+2][lr] = b4.z; Bs[lc+3][lr] = b4.w;
        __syncthreads();
        #pragma unroll
        for (int kk = 0; kk < BK; kk++) {
            float4 a0 = *reinterpret_cast<const float4*>(&As[kk][ty*8]);
            float4 a1 = *reinterpret_cast<const float4*>(&As[kk][ty*8+4]);
            float4 b0 = *reinterpret_cast<const float4*>(&Bs[kk][tx*8]);
            float4 b1 = *reinterpret_cast<const float4*>(&Bs[kk][tx*8+4]);
            float ar[8] = {a0.x,a0.y,a0.z,a0.w,a1.x,a1.y,a1.z,a1.w};
            float br[8] = {b0.x,b0.y,b0.z,b0.w,b1.x,b1.y,b1.z,b1.w};
            #pragma unroll
            for (int i = 0; i < 8; i++)
                #pragma unroll
                for (int j = 0; j < 8; j++)
                    acc[i][j] += ar[i]*br[j];
        }
        __syncthreads();
    }

    const int mbase = blockIdx.y*BM + ty*8;
    const int ebase = blockIdx.x*BN + tx*8;
    #pragma unroll
    for (int i = 0; i < 8; i++) {
        const int m = mbase + i;
        #pragma unroll
        for (int j = 0; j < 8; j++) {
            const int e = ebase + j;
            float v = acc[i][j];
            if (bias) v += bias[e];
            C[(size_t)m*Nc + e] = v;
        }
    }
}

// ---------------------------------------------------------------------------
// RoPE in place on the q and k sections of g_qkv.  (UNCHANGED from passing R13)
// One thread per (n, t, h, i):  linear id over 8*2048*8*32 = 4194304.
// ---------------------------------------------------------------------------
__global__ void rope_inplace_kernel()
{
    const int id = blockIdx.x*blockDim.x + threadIdx.x;
    const int i  = id & 31;
    const int h  = (id >> 5) & 7;
    const int t  = (id >> 8) & (T_SEQ - 1);
    const int n  = id >> 19;

    const double inv = pow(10000.0, -(double)i / 32.0);
    const double ang = (double)t * inv;
    const float  c   = (float)cos(ang);
    const float  s   = (float)sin(ang);

    float* p = g_qkv + ((size_t)(n*T_SEQ + t))*EQKV + h*HDIM;

    {
        float v1 = p[i], v2 = p[i + 32];
        p[i]      = v1*c - v2*s;
        p[i + 32] = v2*c + v1*s;
    }
    {
        float v1 = p[DMODEL + i], v2 = p[DMODEL + i + 32];
        p[DMODEL + i]      = v1*c - v2*s;
        p[DMODEL + i + 32] = v2*c + v1*s;
    }
}

// ---------------------------------------------------------------------------
// Tiled banded attention (fresh derivation).
// One CTA = 32 queries of one (n,h):  i = q0 .. q0+31.
// Band: j - i in [-127, 128]  ->  union over tile: j in [q0-127, q0+159],
// i.e. 287 key rows; slot r = j - (q0-127), r in [0, 286], padded to 288.
// smem: sQ[32][64], sK[288][65], sV[288][65], sP[32][288]  = 48704 floats.
// 8 warps; warp w owns queries wq = 4w..4w+3; lane l owns slots r = l+32s, s<9.
// QK: 36 FMA per 13 LDS (register-blocked).  Softmax: warp butterfly.
// Mask computed from raw j-i band arithmetic.
// ---------------------------------------------------------------------------
#define KT   288
#define KSTR 65
#define ATTN_SMEM_FLOATS (32*64 + 2*KT*KSTR + 32*KT)

__global__ void __launch_bounds__(256) attn_tiled_kernel()
{
    extern __shared__ float sm[];
    float* sQ = sm;                  // [32][64]
    float* sK = sQ + 32*64;          // [288][65]
    float* sV = sK + KT*KSTR;        // [288][65]
    float* sP = sV + KT*KSTR;        // [32][288]

    const int tile = blockIdx.x;     // 0..63
    const int h    = blockIdx.y;     // 0..7
    const int n    = blockIdx.z;     // 0..7
    const int q0    = tile * 32;
    const int kbase = q0 - 127;

    const float* base = g_qkv + (size_t)n*T_SEQ*EQKV + h*HDIM;

    const int tid = threadIdx.x;

    // Load Q tile (rows q0..q0+31, 64 dims) — coalesced 64-float rows.
    for (int idx = tid; idx < 32*64; idx += 256) {
        const int r = idx >> 6, c = idx & 63;
        sQ[r*64 + c] = base[(size_t)(q0 + r)*EQKV + c];
    }
    // Load K/V window (288 rows, zero-padded outside [0,T)).
    for (int idx = tid; idx < KT*64; idx += 256) {
        const int r = idx >> 6, c = idx & 63;
        const int j = kbase + r;
        float kv = 0.f, vv = 0.f;
        if (j >= 0 && j < T_SEQ) {
            const float* row = base + (size_t)j*EQKV;
            kv = row[DMODEL   + c];
            vv = row[2*DMODEL + c];
        }
        sK[r*KSTR + c] = kv;
        sV[r*KSTR + c] = vv;
    }
    __syncthreads();

    const int w = tid >> 5, l = tid & 31;

    // QK scores: 4 queries x 9 key-slots per lane.
    float sc[4][9];
    #pragma unroll
    for (int q = 0; q < 4; q++)
        #pragma unroll
        for (int s = 0; s < 9; s++) sc[q][s] = 0.f;

    #pragma unroll 4
    for (int d = 0; d < 64; d++) {
        float qv[4];
        #pragma unroll
        for (int q = 0; q < 4; q++) qv[q] = sQ[(w*4 + q)*64 + d];
        #pragma unroll
        for (int s = 0; s < 9; s++) {
            const float kv = sK[(l + 32*s)*KSTR + d];
            #pragma unroll
            for (int q = 0; q < 4; q++) sc[q][s] += qv[q]*kv;
        }
    }

    // Per-query: mask (raw band arithmetic) + scale + softmax, write p to sP.
    float inv_den[4];
    #pragma unroll
    for (int q = 0; q < 4; q++) {
        const int i = q0 + w*4 + q;          // query position
        float vals[9];
        float mx = -1e30f;
        #pragma unroll
        for (int s = 0; s < 9; s++) {
            const int r = l + 32*s;
            const int j = kbase + r;         // key position
            const int dj = j - i;
            const bool ok = (j >= 0) && (j < T_SEQ) && (dj >= -127) && (dj <= 128);
            const float v = ok ? sc[q][s]*0.125f : -1e30f;
            vals[s] = v;
            mx = fmaxf(mx, v);
        }
        #pragma unroll
        for (int o = 16; o > 0; o >>= 1) mx = fmaxf(mx, __shfl_xor_sync(0xffffffffu, mx, o));
        float sum = 0.f;
        #pragma unroll
        for (int s = 0; s < 9; s++) {
            const float e = __expf(vals[s] - mx);
            vals[s] = e;
            sum += e;
        }
        #pragma unroll
        for (int o = 16; o > 0; o >>= 1) sum += __shfl_xor_sync(0xffffffffu, sum, o);
        inv_den[q] = 1.f / sum;
        #pragma unroll
        for (int s = 0; s < 9; s++)
            sP[(w*4 + q)*KT + l + 32*s] = vals[s];     // unnormalized exp
    }
    __syncwarp();

    // PV: lane l accumulates dims (l, l+32) for the warp's 4 queries.
    float o0[4] = {0.f,0.f,0.f,0.f}, o1[4] = {0.f,0.f,0.f,0.f};
    #pragma unroll 4
    for (int r = 0; r < KT; r++) {
        const float v0 = sV[r*KSTR + l];
        const float v1 = sV[r*KSTR + l + 32];
        #pragma unroll
        for (int q = 0; q < 4; q++) {
            const float p = sP[(w*4 + q)*KT + r];
            o0[q] += p*v0;
            o1[q] += p*v1;
        }
    }
    #pragma unroll
    for (int q = 0; q < 4; q++) {
        const int i = q0 + w*4 + q;
        float* optr = g_attn + ((size_t)(n*T_SEQ + i))*DMODEL + h*HDIM;
        optr[l]      = o0[q] * inv_den[q];
        optr[l + 32] = o1[q] * inv_den[q];
    }
}

// ---------------------------------------------------------------------------
extern "C" void kernel_launch(void* const* d_in, const int* in_sizes, int n_in,
                              void* d_out, int out_size)
{
    // Bind inputs by element count (robust to ordering); positional fallback.
    const float *x = nullptr, *Wqkv = nullptr, *Wout = nullptr, *bout = nullptr;
    for (int i = 0; i < n_in; i++) {
        long long s = in_sizes[i];
        const float* p = (const float*)d_in[i];
        if      (s == 8388608LL || s == 33554432LL) x    = p;
        else if (s == 786432LL  || s == 3145728LL)  Wqkv = p;
        else if (s == 262144LL  || s == 1048576LL)  Wout = p;
        else if (s == 512LL     || s == 2048LL)     bout = p;
    }
    if (!x    && n_in > 0) x    = (const float*)d_in[0];
    if (!Wqkv && n_in > 1) Wqkv = (const float*)d_in[1];
    if (!Wout && n_in > 2) Wout = (const float*)d_in[2];
    if (!bout && n_in > 3) bout = (const float*)d_in[3];

    float* out = (float*)d_out;
    (void)out_size;

    float* qkv_ptr  = nullptr;
    float* attn_ptr = nullptr;
    cudaGetSymbolAddress((void**)&qkv_ptr,  g_qkv);
    cudaGetSymbolAddress((void**)&attn_ptr, g_attn);

    const int attn_smem = ATTN_SMEM_FLOATS * (int)sizeof(float); // ~190 KB
    cudaFuncSetAttribute(attn_tiled_kernel, cudaFuncAttributeMaxDynamicSharedMemorySize, attn_smem);

    // 1. QKV projection: g_qkv[m][1536] = x[m][:] . Wqkv[e][:]
    {
        dim3 g(EQKV/BN, M_ROWS/BM);   // (12, 128)
        sgemm_nt_kernel<<<g, 256>>>(x, Wqkv, qkv_ptr, DMODEL, EQKV, nullptr);
    }

    // 2. RoPE in place on q,k sections of g_qkv
    {
        const int total = N_BATCH * T_SEQ * NHEAD * 32;  // 4194304
        rope_inplace_kernel<<<total/256, 256>>>();
    }

    // 3. Tiled banded attention -> g_attn
    {
        dim3 g(T_SEQ/32, NHEAD, N_BATCH);  // (64, 8, 8)
        attn_tiled_kernel<<<g, 256, attn_smem>>>();
    }

    // 4. Output projection + bias
    {
        dim3 g(DMODEL/BN, M_ROWS/BM);  // (4, 128)
        sgemm_nt_kernel<<<g, 256>>>(attn_ptr, Wout, out, DMODEL, DMODEL, bout);
    }
}

// round 15
// speedup vs baseline: 2.2503x; 1.6085x over previous
#include <cuda_runtime.h>
#include <math.h>

#define N_BATCH 8
#define T_SEQ   2048
#define DMODEL  512
#define NHEAD   8
#define HDIM    64
#define M_ROWS  (N_BATCH*T_SEQ)   // 16384
#define EQKV    (3*DMODEL)        // 1536

// Scratch (no cudaMalloc allowed)
__device__ float g_qkv[(size_t)M_ROWS*EQKV];    // [n*T+t][1536] : [q|k|v], each h*64+d
__device__ float g_attn[(size_t)M_ROWS*DMODEL]; // [n*T+t][512]
__device__ float g_cos[T_SEQ*32];
__device__ float g_sin[T_SEQ*32];

// ---------------------------------------------------------------------------
// Vanilla NT SGEMM (UNCHANGED — measured at 100% of fp32 FFMA roofline).
// C[m][e] = sum_k A[m][k]*B[e][k] (+bias). 128x128 tile, BK=8, 8x8 microtile.
// ---------------------------------------------------------------------------
#define BM 128
#define BN 128
#define BK 8

__global__ void __launch_bounds__(256) sgemm_nt_kernel(
    const float* __restrict__ A, const float* __restrict__ B,
    float* __restrict__ C, int K, int Nc, const float* __restrict__ bias)
{
    __shared__ __align__(16) float As[BK][BM];
    __shared__ __align__(16) float Bs[BK][BN];

    const int tid = threadIdx.x;
    const int tx  = tid & 15;
    const int ty  = tid >> 4;
    const int lr  = tid >> 1;
    const int lc  = (tid & 1) * 4;

    const float* Ap = A + ((size_t)blockIdx.y*BM + lr)*K + lc;
    const float* Bp = B + ((size_t)blockIdx.x*BN + lr)*K + lc;

    float acc[8][8];
    #pragma unroll
    for (int i = 0; i < 8; i++)
        #pragma unroll
        for (int j = 0; j < 8; j++) acc[i][j] = 0.f;

    for (int k0 = 0; k0 < K; k0 += BK) {
        float4 a4 = *reinterpret_cast<const float4*>(Ap + k0);
        float4 b4 = *reinterpret_cast<const float4*>(Bp + k0);
        As[lc+0][lr] = a4.x; As[lc+1][lr] = a4.y; As[lc+2][lr] = a4.z; As[lc+3][lr] = a4.w;
        Bs[lc+0][lr] = b4.x; Bs[lc+1][lr] = b4.y; Bs[lc+2][lr] = b4.z; Bs[lc+3][lr] = b4.w;
        __syncthreads();
        #pragma unroll
        for (int kk = 0; kk < BK; kk++) {
            float4 a0 = *reinterpret_cast<const float4*>(&As[kk][ty*8]);
            float4 a1 = *reinterpret_cast<const float4*>(&As[kk][ty*8+4]);
            float4 b0 = *reinterpret_cast<const float4*>(&Bs[kk][tx*8]);
            float4 b1 = *reinterpret_cast<const float4*>(&Bs[kk][tx*8+4]);
            float ar[8] = {a0.x,a0.y,a0.z,a0.w,a1.x,a1.y,a1.z,a1.w};
            float br[8] = {b0.x,b0.y,b0.z,b0.w,b1.x,b1.y,b1.z,b1.w};
            #pragma unroll
            for (int i = 0; i < 8; i++)
                #pragma unroll
                for (int j = 0; j < 8; j++)
                    acc[i][j] += ar[i]*br[j];
        }
        __syncthreads();
    }

    const int mbase = blockIdx.y*BM + ty*8;
    const int ebase = blockIdx.x*BN + tx*8;
    #pragma unroll
    for (int i = 0; i < 8; i++) {
        const int m = mbase + i;
        #pragma unroll
        for (int j = 0; j < 8; j++) {
            const int e = ebase + j;
            float v = acc[i][j];
            if (bias) v += bias[e];
            C[(size_t)m*Nc + e] = v;
        }
    }
}

// ---------------------------------------------------------------------------
// RoPE table build: cos/sin[t][i] in fp64 (one-time, 65536 threads).
// ---------------------------------------------------------------------------
__global__ void rope_table_kernel()
{
    const int id = blockIdx.x*blockDim.x + threadIdx.x;   // 0..65535
    const int i = id & 31;
    const int t = id >> 5;
    const double inv = pow(10000.0, -(double)i / 32.0);
    const double ang = (double)t * inv;
    g_cos[id] = (float)cos(ang);
    g_sin[id] = (float)sin(ang);
}

// ---------------------------------------------------------------------------
// RoPE apply in place on q,k sections of g_qkv (fp32, table lookup).
// One thread per (n, t, h, i); id layout identical to R13's passing version.
// ---------------------------------------------------------------------------
__global__ void rope_apply_kernel()
{
    const int id = blockIdx.x*blockDim.x + threadIdx.x;
    const int i  = id & 31;
    const int h  = (id >> 5) & 7;
    const int t  = (id >> 8) & (T_SEQ - 1);
    const int n  = id >> 19;

    const float c = g_cos[t*32 + i];
    const float s = g_sin[t*32 + i];

    float* p = g_qkv + ((size_t)(n*T_SEQ + t))*EQKV + h*HDIM;
    {
        float v1 = p[i], v2 = p[i + 32];
        p[i]      = v1*c - v2*s;
        p[i + 32] = v2*c + v1*s;
    }
    {
        float v1 = p[DMODEL + i], v2 = p[DMODEL + i + 32];
        p[DMODEL + i]      = v1*c - v2*s;
        p[DMODEL + i + 32] = v2*c + v1*s;
    }
}

// ---------------------------------------------------------------------------
// Tiled banded attention v2.
// One CTA = 64 queries of one (n,h): i = q0..q0+63.
// Window union: j in [q0-127, q0+63+128] -> 319 rows, padded to KT2=320.
// slot r = j - (q0-127).  8 warps; warp w owns queries w*8..w*8+7.
// Lane l owns slots r = l + 32s, s = 0..9.
// smem: sQ[64][64], sK[320][65], sV[320][66] = 46016 floats (~180 KB), no sP:
// probabilities stay in registers; PV fetches them via warp shuffle.
// ---------------------------------------------------------------------------
#define KT2   320
#define KSTRK 65
#define KSTRV 66
#define ATTN2_SMEM_FLOATS (64*64 + KT2*KSTRK + KT2*KSTRV)

__global__ void __launch_bounds__(256) attn_tiled64_kernel()
{
    extern __shared__ float sm[];
    float* sQ = sm;                    // [64][64]
    float* sK = sQ + 64*64;            // [320][65]
    float* sV = sK + KT2*KSTRK;        // [320][66]

    const int tile = blockIdx.x;       // 0..31
    const int h    = blockIdx.y;       // 0..7
    const int n    = blockIdx.z;       // 0..7
    const int q0    = tile * 64;
    const int kbase = q0 - 127;

    const float* base = g_qkv + (size_t)n*T_SEQ*EQKV + h*HDIM;
    const int tid = threadIdx.x;

    // Load Q tile (64 rows x 64 dims).
    for (int idx = tid; idx < 64*64; idx += 256) {
        const int r = idx >> 6, c = idx & 63;
        sQ[r*64 + c] = base[(size_t)(q0 + r)*EQKV + c];
    }
    // Load K/V window (320 rows, zero-padded outside [0,T)).
    for (int idx = tid; idx < KT2*64; idx += 256) {
        const int r = idx >> 6, c = idx & 63;
        const int j = kbase + r;
        float kv = 0.f, vv = 0.f;
        if (j >= 0 && j < T_SEQ) {
            const float* row = base + (size_t)j*EQKV;
            kv = row[DMODEL   + c];
            vv = row[2*DMODEL + c];
        }
        sK[r*KSTRK + c] = kv;
        sV[r*KSTRV + c] = vv;
    }
    __syncthreads();

    const int w = tid >> 5, l = tid & 31;

    // QK scores: 8 queries x 10 slots per lane.
    float sc[8][10];
    #pragma unroll
    for (int q = 0; q < 8; q++)
        #pragma unroll
        for (int s = 0; s < 10; s++) sc[q][s] = 0.f;

    #pragma unroll 2
    for (int d = 0; d < 64; d++) {
        float qv[8];
        #pragma unroll
        for (int q = 0; q < 8; q++) qv[q] = sQ[(w*8 + q)*64 + d];  // broadcast
        #pragma unroll
        for (int s = 0; s < 10; s++) {
            const float kv = sK[(l + 32*s)*KSTRK + d];
            #pragma unroll
            for (int q = 0; q < 8; q++) sc[q][s] += qv[q]*kv;
        }
    }

    // Mask + scale + softmax per query; keep unnormalized exp in sc registers.
    float inv_den[8];
    #pragma unroll
    for (int q = 0; q < 8; q++) {
        const int i = q0 + w*8 + q;
        float mx = -1e30f;
        #pragma unroll
        for (int s = 0; s < 10; s++) {
            const int r  = l + 32*s;
            const int j  = kbase + r;
            const int dj = j - i;
            const bool ok = (j >= 0) && (j < T_SEQ) && (dj >= -127) && (dj <= 128);
            const float v = ok ? sc[q][s]*0.125f : -1e30f;
            sc[q][s] = v;
            mx = fmaxf(mx, v);
        }
        #pragma unroll
        for (int o = 16; o > 0; o >>= 1) mx = fmaxf(mx, __shfl_xor_sync(0xffffffffu, mx, o));
        float sum = 0.f;
        #pragma unroll
        for (int s = 0; s < 10; s++) {
            const float e = __expf(sc[q][s] - mx);
            sc[q][s] = e;
            sum += e;
        }
        #pragma unroll
        for (int o = 16; o > 0; o >>= 1) sum += __shfl_xor_sync(0xffffffffu, sum, o);
        inv_den[q] = 1.f / sum;
    }

    // PV: lane l owns output dims (2l, 2l+1); p values fetched via shuffle.
    float ox[8] = {0,0,0,0,0,0,0,0}, oy[8] = {0,0,0,0,0,0,0,0};
    #pragma unroll
    for (int s = 0; s < 10; s++) {
        #pragma unroll 4
        for (int lsrc = 0; lsrc < 32; lsrc++) {
            const int r = 32*s + lsrc;
            const float2 v2 = *reinterpret_cast<const float2*>(&sV[r*KSTRV + 2*l]);
            #pragma unroll
            for (int q = 0; q < 8; q++) {
                const float p = __shfl_sync(0xffffffffu, sc[q][s], lsrc);
                ox[q] += p*v2.x;
                oy[q] += p*v2.y;
            }
        }
    }

    #pragma unroll
    for (int q = 0; q < 8; q++) {
        const int i = q0 + w*8 + q;
        float2 o2 = make_float2(ox[q]*inv_den[q], oy[q]*inv_den[q]);
        *reinterpret_cast<float2*>(
            g_attn + ((size_t)(n*T_SEQ + i))*DMODEL + h*HDIM + 2*l) = o2;
    }
}

// ---------------------------------------------------------------------------
extern "C" void kernel_launch(void* const* d_in, const int* in_sizes, int n_in,
                              void* d_out, int out_size)
{
    // Bind inputs by element count; positional fallback.
    const float *x = nullptr, *Wqkv = nullptr, *Wout = nullptr, *bout = nullptr;
    for (int i = 0; i < n_in; i++) {
        long long s = in_sizes[i];
        const float* p = (const float*)d_in[i];
        if      (s == 8388608LL || s == 33554432LL) x    = p;
        else if (s == 786432LL  || s == 3145728LL)  Wqkv = p;
        else if (s == 262144LL  || s == 1048576LL)  Wout = p;
        else if (s == 512LL     || s == 2048LL)     bout = p;
    }
    if (!x    && n_in > 0) x    = (const float*)d_in[0];
    if (!Wqkv && n_in > 1) Wqkv = (const float*)d_in[1];
    if (!Wout && n_in > 2) Wout = (const float*)d_in[2];
    if (!bout && n_in > 3) bout = (const float*)d_in[3];

    float* out = (float*)d_out;
    (void)out_size;

    float* qkv_ptr  = nullptr;
    float* attn_ptr = nullptr;
    cudaGetSymbolAddress((void**)&qkv_ptr,  g_qkv);
    cudaGetSymbolAddress((void**)&attn_ptr, g_attn);

    const int attn_smem = ATTN2_SMEM_FLOATS * (int)sizeof(float); // ~180 KB
    cudaFuncSetAttribute(attn_tiled64_kernel, cudaFuncAttributeMaxDynamicSharedMemorySize, attn_smem);

    // 1. QKV projection
    {
        dim3 g(EQKV/BN, M_ROWS/BM);   // (12, 128)
        sgemm_nt_kernel<<<g, 256>>>(x, Wqkv, qkv_ptr, DMODEL, EQKV, nullptr);
    }

    // 2. RoPE: build table (fp64, tiny), then fp32 apply
    {
        rope_table_kernel<<<(T_SEQ*32)/256, 256>>>();
        const int total = N_BATCH * T_SEQ * NHEAD * 32;  // 4194304
        rope_apply_kernel<<<total/256, 256>>>();
    }

    // 3. Tiled banded attention (64-query tiles) -> g_attn
    {
        dim3 g(T_SEQ/64, NHEAD, N_BATCH);  // (32, 8, 8)
        attn_tiled64_kernel<<<g, 256, attn_smem>>>();
    }

    // 4. Output projection + bias
    {
        dim3 g(DMODEL/BN, M_ROWS/BM);  // (4, 128)
        sgemm_nt_kernel<<<g, 256>>>(attn_ptr, Wout, out, DMODEL, DMODEL, bout);
    }
}